// round 16
// baseline (speedup 1.0000x reference)
#include <cuda_runtime.h>
#include <cuda_bf16.h>
#include <math.h>

#define ETA 0.1f
#define THETA 4.0f
#define NN 4096
#define THREADS 128

typedef unsigned int u32;

// ---- smem float offsets ----
#define F_EA   64
#define F_EA2  (64 + 4096)
#define F_EA3  (64 + 8192)
#define F_XH   (64 + 12288)           // u32[2048] bf16x2 A-fragments (high)
#define F_XL   (F_XH + 2048)          // u32[2048] (low)
#define F_YH   (F_XH + 4096)          // u32[2048] B-fragments (high)
#define F_YL   (F_XH + 6144)          // u32[2048] (low)
#define SMEM_FLOATS (64 + 12288 + 8192)   // 20544 floats = 82176 B (2 CTAs/SM)

// per-ROW swizzle xor: conflict-free fragment passes (R15-proven)
__device__ __forceinline__ int swi(int r, int c4) {
    return (r << 6) + ((c4 ^ (r & 7)) << 2);
}

__device__ __forceinline__ u32 packbf(float a, float b) {
    __nv_bfloat162 v;
    v.x = __float2bfloat16(a);
    v.y = __float2bfloat16(b);
    return *reinterpret_cast<u32*>(&v);
}
// split (a,b) into bf16 high pair and bf16 residual-low pair
__device__ __forceinline__ void splitpk(float a, float b, u32& hi, u32& lo) {
    __nv_bfloat16 ha = __float2bfloat16(a), hb = __float2bfloat16(b);
    __nv_bfloat162 h; h.x = ha; h.y = hb;
    hi = *reinterpret_cast<u32*>(&h);
    lo = packbf(a - __bfloat162float(ha), b - __bfloat162float(hb));
}

#define MMA(c, a0, a1, a2, a3, b0, b1) \
    asm volatile("mma.sync.aligned.m16n8k16.row.col.f32.bf16.bf16.f32 " \
        "{%0,%1,%2,%3},{%4,%5,%6,%7},{%8,%9},{%0,%1,%2,%3};" \
        : "+f"((c)[0]), "+f"((c)[1]), "+f"((c)[2]), "+f"((c)[3]) \
        : "r"(a0), "r"(a1), "r"(a2), "r"(a3), "r"(b0), "r"(b1))

// B-fragment split-pack from an fp32 smem matrix (used once: Y = A2 at step 2)
__device__ __forceinline__ void ysplit(float* smx, const float* src, int t) {
    u32* YH = (u32*)(smx + F_YH);
    u32* YL = (u32*)(smx + F_YL);
#pragma unroll
    for (int q = 0; q < 16; q++) {
        const int p = t + q * 128;
        const int T = p & 31, b = (p >> 5) & 1, j = (p >> 6) & 7, kk = p >> 9;
        const int g = T >> 2, tg = T & 3;
        const int k = (kk * 8 + b * 4 + tg) * 2;
        const int n = 8 * j + g;
        const int o0 = swi(k, n >> 2) + (n & 3);
        const int o1 = swi(k + 1, n >> 2) + (n & 3);
        u32 hi, lo;
        splitpk(src[o0], src[o1], hi, lo);
        YH[p] = hi; YL[p] = lo;
    }
}
// A-fragment split-pack (initial only)
__device__ __forceinline__ void xsplit(float* smx, const float* src, int t) {
    u32* XH = (u32*)(smx + F_XH);
    u32* XL = (u32*)(smx + F_XL);
#pragma unroll
    for (int q = 0; q < 16; q++) {
        const int p = t + q * 128;
        const int T = p & 31, reg = (p >> 5) & 3, kk = (p >> 7) & 3, w = p >> 9;
        const int r8 = reg & 1, kh = reg >> 1;
        const int row = w * 16 + r8 * 8 + (T >> 2);
        const int k = kk * 16 + kh * 8 + (T & 3) * 2;
        const int off = swi(row, k >> 2) + (k & 3);
        u32 hi, lo;
        splitpk(src[off], src[off + 1], hi, lo);
        XH[p] = hi; XL[p] = lo;
    }
}

__global__ void __launch_bounds__(THREADS, 2)
meg_update_kernel(const float* __restrict__ gR,
                  const float* __restrict__ gG,
                  float* __restrict__ gOut) {
    extern __shared__ float smx[];
    const int t = threadIdx.x;
    const int w = t >> 5, lane = t & 31;
    const int g = lane >> 2, tg = lane & 3;

    float* EA  = smx + F_EA;
    float* EA2 = smx + F_EA2;
    float* EA3 = smx + F_EA3;
    u32* XH = (u32*)(smx + F_XH);
    u32* XL = (u32*)(smx + F_XL);
    u32* YH = (u32*)(smx + F_YH);
    u32* YL = (u32*)(smx + F_YL);

    const size_t gb = (size_t)blockIdx.x * NN;
    const float4* R4 = (const float4*)(gR + gb);
    const float4* G4 = (const float4*)(gG + gb);
    float* gO = gOut + gb;

    // ---- G -> EA3 (staging, swizzled) ----
#pragma unroll
    for (int q = 0; q < 8; q++) {
        const int e4 = t + q * 128, r = e4 >> 4, c4 = e4 & 15;
        *(float4*)(EA3 + swi(r, c4)) = G4[e4];
    }
    __syncthreads();
    // ---- A = log(R) - ETA*(G - G^T) -> EA ----
#pragma unroll
    for (int q = 0; q < 8; q++) {
        const int e4 = t + q * 128, r = e4 >> 4, c4 = e4 & 15, cb = c4 << 2;
        const float4 rv = R4[e4];
        const float4 gv = *(const float4*)(EA3 + swi(r, c4));
        const float g0 = EA3[swi(cb + 0, r >> 2) + (r & 3)];
        const float g1 = EA3[swi(cb + 1, r >> 2) + (r & 3)];
        const float g2 = EA3[swi(cb + 2, r >> 2) + (r & 3)];
        const float g3 = EA3[swi(cb + 3, r >> 2) + (r & 3)];
        float4 a;
        a.x = logf(rv.x) - ETA * (gv.x - g0);
        a.y = logf(rv.y) - ETA * (gv.y - g1);
        a.z = logf(rv.z) - ETA * (gv.z - g2);
        a.w = logf(rv.w) - ETA * (gv.w - g3);
        *(float4*)(EA + swi(r, c4)) = a;
    }
    __syncthreads();
    // ---- inf-norm -> nsq ----
    if (t < 64) {
        float rs = 0.f;
#pragma unroll
        for (int c = 0; c < 16; c++) {
            const float4 v = *(const float4*)(EA + swi(t, c));
            rs += fabsf(v.x) + fabsf(v.y) + fabsf(v.z) + fabsf(v.w);
        }
#pragma unroll
        for (int o = 16; o > 0; o >>= 1) rs = fmaxf(rs, __shfl_xor_sync(~0u, rs, o));
        if ((t & 31) == 0) smx[4 + (t >> 5)] = rs;
    }
    __syncthreads();
    if (t == 0) {
        const float nrm = fmaxf(smx[4], smx[5]);
        int s = 0;
        if (nrm > THETA && isfinite(nrm)) {
            s = (int)ceilf(log2f(nrm / THETA));
            if (s < 0) s = 0;
            if (s > 30) s = 30;
        }
        ((int*)smx)[6] = s;
    }
    __syncthreads();
    const int nsq = ((int*)smx)[6];
    const float scale = exp2f((float)-nsq);
#pragma unroll
    for (int q = 0; q < 8; q++) {
        float4* p = (float4*)EA + (t + q * 128);
        float4 v = *p; v.x *= scale; v.y *= scale; v.z *= scale; v.w *= scale; *p = v;
    }
    __syncthreads();

    // ---- initial fragments: X = A, Y = A ----
    xsplit(smx, EA, t);
    ysplit(smx, EA, t);
    __syncthreads();

    const float c0 = 1.f, c1 = 1.f, c2 = .5f, c3 = (float)(1.0 / 6.0),
        c4f = (float)(1.0 / 24.0), c5 = (float)(1.0 / 120.0), c6 = (float)(1.0 / 720.0),
        c7 = (float)(1.0 / 5040.0), c8 = (float)(1.0 / 40320.0), c9 = (float)(1.0 / 362880.0),
        c10 = (float)(1.0 / 3628800.0), c11 = (float)(1.0 / 39916800.0),
        c12 = (float)(1.0 / 479001600.0), c13 = (float)(1.0 / 6227020800.0),
        c14 = (float)(1.0 / 87178291200.0), c15 = (float)(1.0 / 1307674368000.0),
        c16 = (float)(1.0 / 20922789888000.0);

    const int nsteps = 6 + nsq;
#pragma unroll 1
    for (int step = 0; step < nsteps; step++) {
        // only A2 (step 2's Y) still needs the fp32->fragment path
        if (step == 2) {
            ysplit(smx, EA2, t);
            __syncthreads();
        }

        // ---- GEMM: 96 HMMA per warp ----
        float acc[8][4];
#pragma unroll
        for (int j = 0; j < 8; j++) { acc[j][0] = acc[j][1] = acc[j][2] = acc[j][3] = 0.f; }

#pragma unroll
        for (int kk = 0; kk < 4; kk++) {
            u32 ah[4], al[4];
#pragma unroll
            for (int r = 0; r < 4; r++) {
                const int ix = (w * 4 + kk) * 128 + r * 32 + lane;
                ah[r] = ((const u32*)(smx + F_XH))[ix];
                al[r] = ((const u32*)(smx + F_XL))[ix];
            }
            u32 bh[8][2], bl[8][2];
#pragma unroll
            for (int j = 0; j < 8; j++) {
                const int ix = kk * 512 + j * 64 + lane;
                bh[j][0] = YH[ix];      bh[j][1] = YH[ix + 32];
                bl[j][0] = YL[ix];      bl[j][1] = YL[ix + 32];
            }
#pragma unroll
            for (int j = 0; j < 8; j++) MMA(acc[j], ah[0], ah[1], ah[2], ah[3], bh[j][0], bh[j][1]);
#pragma unroll
            for (int j = 0; j < 8; j++) MMA(acc[j], al[0], al[1], al[2], al[3], bh[j][0], bh[j][1]);
#pragma unroll
            for (int j = 0; j < 8; j++) MMA(acc[j], ah[0], ah[1], ah[2], ah[3], bl[j][0], bl[j][1]);
        }

        // ---- step configuration ----
        const bool last = (step == nsteps - 1);
        float* dstF = 0;                         // fp32 smem store (EA2/EA3 only)
        int mode = 0;                            // 0 plain, 1 horner, 2 seed
        int xsp = 0;
        float d0 = 0.f, d1 = 0.f, d2 = 0.f, d3 = 0.f;
        if (step == 0)      { dstF = EA2; xsp = 1; }
        else if (step == 1) { dstF = EA3; }
        else if (step == 2) { mode = 2; xsp = 1; }
        else if (step == 3) { mode = 1; d0 = c8;  d1 = c9; d2 = c10; d3 = c11; }
        else if (step == 4) { mode = 1; d0 = c4f; d1 = c5; d2 = c6;  d3 = c7; }
        else if (step == 5) { mode = 1; d0 = c0;  d1 = c1; d2 = c2;  d3 = c3; xsp = 1; }
        else                { xsp = 1; }
        const bool yprod = (step >= 2) && !last;
        if (last) xsp = 0;

        // Y buffer is read by ALL warps in the GEMM above and written
        // per-warp below: separate the phases.
        if (yprod) __syncthreads();

        // ---- epilogue ----
#pragma unroll
        for (int j = 0; j < 8; j++) {
#pragma unroll
            for (int ch = 0; ch < 2; ch++) {
                const int row = 16 * w + g + ch * 8;
                const int col = 8 * j + 2 * tg;     // even -> float2-aligned
                const int off = swi(row, col >> 2) + (col & 3);
                float vx = acc[j][2 * ch + 0];
                float vy = acc[j][2 * ch + 1];
                if (mode == 1) {
                    const float2 e1 = *(const float2*)(EA  + off);
                    const float2 e2 = *(const float2*)(EA2 + off);
                    const float2 e3 = *(const float2*)(EA3 + off);
                    vx += fmaf(d1, e1.x, fmaf(d2, e2.x, d3 * e3.x));
                    vy += fmaf(d1, e1.y, fmaf(d2, e2.y, d3 * e3.y));
                    if (row == col)     vx += d0;
                    if (row == col + 1) vy += d0;
                } else if (mode == 2) {
                    const float2 e1 = *(const float2*)(EA  + off);
                    const float2 e2 = *(const float2*)(EA2 + off);
                    const float2 e3 = *(const float2*)(EA3 + off);
                    vx = fmaf(c13, e1.x, fmaf(c14, e2.x, fmaf(c15, e3.x, c16 * vx)));
                    vy = fmaf(c13, e1.y, fmaf(c14, e2.y, fmaf(c15, e3.y, c16 * vy)));
                    if (row == col)     vx += c12;
                    if (row == col + 1) vy += c12;
                }
                // repack must see POST-epilogue values except in seed mode
                // (step 2: X must become A4 while vx/vy hold the seed S).
                if (mode != 2) { acc[j][2 * ch + 0] = vx; acc[j][2 * ch + 1] = vy; }

                if (dstF) *(float2*)(dstF + off) = make_float2(vx, vy);
                if (last) *(float2*)(gO + row * 64 + col) = make_float2(vx, vy);

                if (yprod) {
                    // direct Y-fragment production (shuffle transpose):
                    // element rows pair (k even, k+1) for col n; partner row
                    // lives in lane^4. Verified against ysplit slot-by-slot.
                    const float rx = __shfl_xor_sync(~0u, vx, 4);
                    const float ry = __shfl_xor_sync(~0u, vy, 4);
                    const float a = (g & 1) ? ry : vx;   // even row value
                    const float b = (g & 1) ? vy : rx;   // odd row value
                    u32 hi, lo;
                    splitpk(a, b, hi, lo);
                    const int p = 8 * tg + 4 * (g & 1) + (g >> 1)
                                + 32 * ch + 64 * j + 512 * w;
                    YH[p] = hi; YL[p] = lo;
                }
            }
            if (xsp) {   // repack into next step's A-fragments (warp-private)
                const int ix = ((w * 4 + (j >> 1)) * 4 + (j & 1) * 2) * 32 + lane;
                splitpk(acc[j][0], acc[j][1], XH[ix], XL[ix]);
                splitpk(acc[j][2], acc[j][3], XH[ix + 32], XL[ix + 32]);
            }
        }
        __syncthreads();
    }
}

extern "C" void kernel_launch(void* const* d_in, const int* in_sizes, int n_in,
                              void* d_out, int out_size) {
    const float* R = (const float*)d_in[0];
    const float* G = (const float*)d_in[1];
    float* out = (float*)d_out;
    const int batch = in_sizes[0] / NN;
    const size_t smem = (size_t)SMEM_FLOATS * sizeof(float);   // 82176 B

    static bool attr_set = false;
    if (!attr_set) {
        cudaFuncSetAttribute(meg_update_kernel,
                             cudaFuncAttributeMaxDynamicSharedMemorySize, (int)smem);
        attr_set = true;
    }
    meg_update_kernel<<<batch, THREADS, smem>>>(R, G, out);
}